// round 17
// baseline (speedup 1.0000x reference)
#include <cuda_runtime.h>
#include <cuda_fp16.h>
#include <cstdint>

#define D       64
#define HW      4096
#define KCODES  1024
#define NTOK    65536

#define ESCALE    1024.0f
#define NEG2EINV (-0.001953125f)     // -2/1024 : d' = 64 + sse - 2*dot
#define BITS60    0x42700000u        // bits(60.0f), key bias

// ---------------- device scratch (no allocation allowed) -------------------
__device__ uint4 g_Eh4[8192];        // 128KB: hi-plane B fragments, all 1024 codes
__device__ float g_sse[KCODES];
__device__ float g_cbT[D * KCODES];  // 256KB: transposed codebook [k][n]
__device__ int   g_nfb;              // fallback count
__device__ int   g_fb[NTOK];         // fallback token list
__device__ int   g_nrf;              // refine count
__device__ uint2 g_rf[NTOK];         // refine list: {row, i1 | i2<<16}

__device__ __forceinline__ uint32_t packh(float x0, float x1) {
    uint32_t r;
    asm("cvt.rn.f16x2.f32 %0, %1, %2;" : "=r"(r) : "f"(x1), "f"(x0));
    return r;
}

// C += A(f16 16x16) * B(f16 16x8), fp32 accumulate.
__device__ __forceinline__ void mma_f16(float c[4], const uint32_t* a,
                                        uint32_t b0, uint32_t b1) {
    asm("mma.sync.aligned.m16n8k16.row.col.f32.f16.f16.f32 "
        "{%0,%1,%2,%3}, {%4,%5,%6,%7}, {%8,%9}, {%0,%1,%2,%3};"
        : "+f"(c[0]), "+f"(c[1]), "+f"(c[2]), "+f"(c[3])
        : "r"(a[0]), "r"(a[1]), "r"(a[2]), "r"(a[3]), "r"(b0), "r"(b1));
}

// ---------------- prep: fragments (ks-contiguous) + sse + transpose --------
__global__ void vq_prep(const float* __restrict__ cb) {
    int id = blockIdx.x * blockDim.x + threadIdx.x;   // 256*256 = 65536
    if (id == 0) { g_nfb = 0; g_nrf = 0; }
    int n = id >> 6, k = id & 63;
    float e = cb[id];
    g_cbT[k * KCODES + n] = e;                  // transpose for fallback
    __half hi = __float2half(e * ESCALE);
    int ntile = n >> 3, nrow = n & 7;
    int kstep = k >> 4, kin = k & 15;
    int j    = kin >> 3;
    int cb4  = (kin & 7) >> 1;
    int elem = k & 1;
    int lane = nrow * 4 + cb4;
    int slot = (ntile * 32 + lane) * 4 + kstep;   // uint2 slots, ks contiguous
    ((__half*)g_Eh4)[slot * 4 + j * 2 + elem] = hi;
    if (k == 0) {   // sequential row sum, unscaled
        const float* r = cb + n * D;
        float s = 0.0f;
        for (int d0 = 0; d0 < D; ++d0) s += r[d0] * r[d0];
        g_sse[n] = s;
    }
}

#define SMEM_REQ (131072 + 8192)
#define THREADS  1024

// branchless sorted top-3 insert of packed key v into (m1 <= m2 <= m3)
#define INS3(m1, m2, m3, v)                       \
    {                                             \
        uint32_t _t = max(m1, v);                 \
        m1 = min(m1, v);                          \
        uint32_t _t2 = max(m2, _t);               \
        m2 = min(m2, _t);                         \
        m3 = min(m3, _t2);                        \
    }

// ---------------- main: hi-plane screening, 32 warps/CTA -------------------
__global__ void __launch_bounds__(THREADS, 1)
vq_main(const float* __restrict__ input, const float* __restrict__ cb,
        float* __restrict__ out) {
    extern __shared__ char smraw[];
    uint4* sB4  = (uint4*)smraw;                 // 8192 uint4 = 128KB
    float* sSse = (float*)(smraw + 131072);      // exact sse, 1024 floats
    float* sSsp = (float*)(smraw + 135168);      // 64 + sse,  1024 floats

    const int tid  = threadIdx.x;
    const int w    = tid >> 5;    // 0..31
    const int lane = tid & 31;
    const int grp  = lane >> 2;
    const int cb4  = lane & 3;

    // stage ALL 1024 codes' hi fragments + sse (+64-biased copy) once
    {
        #pragma unroll
        for (int i = 0; i < 8; ++i)
            sB4[tid + i * THREADS] = g_Eh4[tid + i * THREADS];
        float s = g_sse[tid];
        sSse[tid] = s;
        sSsp[tid] = 64.0f + s;
    }
    __syncthreads();

    const int base = blockIdx.x * 512 + w * 16;

    // ---- A hi fragment: 16 tokens ----
    uint32_t Ahi[16];
    float ssx0, ssx1;
    {
        const int row0 = base + grp;
        const int b    = row0 >> 12;
        const int hw   = row0 & (HW - 1);
        const float* p0 = input + (size_t)b * D * HW + hw;
        const float* p1 = p0 + 8;
        float s0 = 0.0f, s1 = 0.0f;
        #pragma unroll
        for (int ks = 0; ks < 4; ++ks) {
            const int k0 = ks * 16 + 2 * cb4;
            float xa, xb;
            xa = p0[(size_t)k0 * HW];        xb = p0[(size_t)(k0 + 1) * HW];
            s0 = fmaf(xa, xa, s0);           s0 = fmaf(xb, xb, s0);
            Ahi[ks * 4 + 0] = packh(xa, xb);
            xa = p1[(size_t)k0 * HW];        xb = p1[(size_t)(k0 + 1) * HW];
            s1 = fmaf(xa, xa, s1);           s1 = fmaf(xb, xb, s1);
            Ahi[ks * 4 + 1] = packh(xa, xb);
            xa = p0[(size_t)(k0 + 8) * HW];  xb = p0[(size_t)(k0 + 9) * HW];
            s0 = fmaf(xa, xa, s0);           s0 = fmaf(xb, xb, s0);
            Ahi[ks * 4 + 2] = packh(xa, xb);
            xa = p1[(size_t)(k0 + 8) * HW];  xb = p1[(size_t)(k0 + 9) * HW];
            s1 = fmaf(xa, xa, s1);           s1 = fmaf(xb, xb, s1);
            Ahi[ks * 4 + 3] = packh(xa, xb);
        }
        s0 += __shfl_xor_sync(0xffffffffu, s0, 1);
        s0 += __shfl_xor_sync(0xffffffffu, s0, 2);
        s1 += __shfl_xor_sync(0xffffffffu, s1, 1);
        s1 += __shfl_xor_sync(0xffffffffu, s1, 2);
        ssx0 = s0;
        ssx1 = s1;
    }

    // packed top-3 per token: key = bits(d')*1024 + (kg - BITS60*1024)
    uint32_t m1[2] = {0xFFFFFFFFu, 0xFFFFFFFFu};
    uint32_t m2[2] = {0xFFFFFFFFu, 0xFFFFFFFFu};
    uint32_t m3[2] = {0xFFFFFFFFu, 0xFFFFFFFFu};
    const uint32_t KBIAS = 0u - BITS60 * 1024u;

    // ---- screening: hi*hi only, all 1024 codes, branchless epilogue ----
    #pragma unroll 4
    for (int nt = 0; nt < 128; ++nt) {
        uint4 B01 = sB4[(nt * 32 + lane) * 2];
        uint4 B23 = sB4[(nt * 32 + lane) * 2 + 1];
        float C[4] = {0.0f, 0.0f, 0.0f, 0.0f};
        mma_f16(C, &Ahi[0],  B01.x, B01.y);
        mma_f16(C, &Ahi[4],  B01.z, B01.w);
        mma_f16(C, &Ahi[8],  B23.x, B23.y);
        mma_f16(C, &Ahi[12], B23.z, B23.w);
        const int kg = nt * 8 + 2 * cb4;
        float2 sp = *(const float2*)&sSsp[kg];
        float d00 = fmaf(C[0], NEG2EINV, sp.x);
        float d01 = fmaf(C[1], NEG2EINV, sp.y);
        float d10 = fmaf(C[2], NEG2EINV, sp.x);
        float d11 = fmaf(C[3], NEG2EINV, sp.y);
        const uint32_t kb = KBIAS + (uint32_t)kg;
        uint32_t u00 = __float_as_uint(d00) * 1024u + kb;
        uint32_t u01 = __float_as_uint(d01) * 1024u + kb + 1u;
        uint32_t u10 = __float_as_uint(d10) * 1024u + kb;
        uint32_t u11 = __float_as_uint(d11) * 1024u + kb + 1u;
        INS3(m1[0], m2[0], m3[0], u00);
        INS3(m1[0], m2[0], m3[0], u01);
        INS3(m1[1], m2[1], m3[1], u10);
        INS3(m1[1], m2[1], m3[1], u11);
    }

    // ---- merge top-3 across the 4 cb4 lanes (packed => lex-correct) ----
    #pragma unroll
    for (int off = 1; off <= 2; off <<= 1) {
        #pragma unroll
        for (int h = 0; h < 2; ++h) {
            uint32_t o1 = __shfl_xor_sync(0xffffffffu, m1[h], off);
            uint32_t o2 = __shfl_xor_sync(0xffffffffu, m2[h], off);
            uint32_t o3 = __shfl_xor_sync(0xffffffffu, m3[h], off);
            INS3(m1[h], m2[h], m3[h], o1);
            INS3(m1[h], m2[h], m3[h], o2);
            INS3(m1[h], m2[h], m3[h], o3);
        }
    }

    // ---- flags + provisional output (lanes cb4 0/1 own token h=cb4) ----
    if (cb4 < 2) {
        const int h    = cb4;
        const int row  = base + grp + h * 8;
        const int b    = row >> 12;
        const int hw   = row & (HW - 1);
        const float ssx = h ? ssx1 : ssx0;

        const int i1 = (int)(m1[h] & 1023u);
        const int i2 = (int)(m2[h] & 1023u);
        float dscr1 = __uint_as_float((m1[h] >> 10) + BITS60);
        float dscr2 = __uint_as_float((m2[h] >> 10) + BITS60);
        float dscr3 = __uint_as_float((m3[h] >> 10) + BITS60);
        float T = fmaf(sqrtf(ssx), 3.1e-5f, 5.0e-5f);

        if (dscr3 - dscr1 < T) {
            // third code within screening bound: full exact scan later
            int slot = atomicAdd(&g_nfb, 1);
            g_fb[slot] = row;
        } else if (dscr2 - dscr1 < T) {
            // only {i1, i2} can win: exact pair refine later
            int slot = atomicAdd(&g_nrf, 1);
            g_rf[slot] = make_uint2((uint32_t)row,
                                    (uint32_t)i1 | ((uint32_t)i2 << 16));
        }

        const float4* e  = (const float4*)cb + i1 * (D / 4);
        float*        op = out + (size_t)b * D * HW + hw;
        #pragma unroll
        for (int j = 0; j < D / 4; ++j) {
            float4 v = __ldg(e + j);
            op[(size_t)(4 * j + 0) * HW] = v.x;
            op[(size_t)(4 * j + 1) * HW] = v.y;
            op[(size_t)(4 * j + 2) * HW] = v.z;
            op[(size_t)(4 * j + 3) * HW] = v.w;
        }
    }
}

// ------- refine: exact fp32 pair compare, warp per token -------------------
__global__ void __launch_bounds__(256, 1)
vq_rf(const float* __restrict__ input, const float* __restrict__ cb,
      float* __restrict__ out) {
    const int n = g_nrf;
    const int gw   = (blockIdx.x * 256 + threadIdx.x) >> 5;   // 1024 warps
    const int lane = threadIdx.x & 31;

    for (int t = gw; t < n; t += 1024) {
        const uint2 e  = g_rf[t];
        const int row  = (int)e.x;
        const int i1   = (int)(e.y & 0xFFFFu);
        const int i2   = (int)(e.y >> 16);
        const int b    = row >> 12;
        const int hw   = row & (HW - 1);
        const float* xp = input + (size_t)b * D * HW + hw;

        float xa = xp[(size_t)lane * HW];
        float xb = xp[(size_t)(lane + 32) * HW];
        float ea1 = __ldg(cb + i1 * D + lane);
        float eb1 = __ldg(cb + i1 * D + lane + 32);
        float ea2 = __ldg(cb + i2 * D + lane);
        float eb2 = __ldg(cb + i2 * D + lane + 32);
        float d1 = fmaf(xa, ea1, xb * eb1);
        float d2 = fmaf(xa, ea2, xb * eb2);
        float ss = fmaf(xa, xa, xb * xb);
        #pragma unroll
        for (int off = 16; off >= 1; off >>= 1) {
            d1 += __shfl_xor_sync(0xffffffffu, d1, off);
            d2 += __shfl_xor_sync(0xffffffffu, d2, off);
            ss += __shfl_xor_sync(0xffffffffu, ss, off);
        }
        float r1 = (ss + __ldg(&g_sse[i1])) - 2.0f * d1;
        float r2 = (ss + __ldg(&g_sse[i2])) - 2.0f * d2;
        int win = i1;
        if (r2 < r1 || (r2 == r1 && i2 < i1)) win = i2;

        float* op = out + (size_t)b * D * HW + hw;
        op[(size_t)lane * HW]        = __ldg(cb + win * D + lane);
        op[(size_t)(lane + 32) * HW] = __ldg(cb + win * D + lane + 32);
    }
}

// ------- fallback: exact fp32 full scan, warp/token, coalesced via g_cbT ---
__global__ void __launch_bounds__(256, 1)
vq_fb(const float* __restrict__ input, const float* __restrict__ cb,
      float* __restrict__ out) {
    const int n = g_nfb;
    const int gw   = (blockIdx.x * 256 + threadIdx.x) >> 5;   // 1024 warps
    const int lane = threadIdx.x & 31;

    for (int t = gw; t < n; t += 1024) {
        const int row = g_fb[t];
        const int b   = row >> 12;
        const int hw  = row & (HW - 1);
        const float* xp = input + (size_t)b * D * HW + hw;

        float xa = xp[(size_t)lane * HW];
        float xb = xp[(size_t)(lane + 32) * HW];
        float xr[64];
        #pragma unroll
        for (int k = 0; k < 64; ++k)
            xr[k] = __shfl_sync(0xffffffffu, (k < 32) ? xa : xb, k & 31);
        float ssx = 0.0f;
        #pragma unroll
        for (int k = 0; k < 64; ++k) ssx = fmaf(xr[k], xr[k], ssx);

        float bd = 3.4e38f;
        int   bi = 0;
        #pragma unroll 1
        for (int j = 0; j < 32; ++j) {
            const int c = lane + 32 * j;    // ascending per lane
            float dot = 0.0f;
            #pragma unroll
            for (int k = 0; k < 64; ++k)    // coalesced: lanes read consecutive n
                dot = fmaf(xr[k], __ldg(&g_cbT[k * KCODES + c]), dot);
            float dist = (ssx + __ldg(&g_sse[c])) - 2.0f * dot;
            if (dist < bd) { bd = dist; bi = c; }
        }
        #pragma unroll
        for (int off = 16; off >= 1; off >>= 1) {
            float od = __shfl_xor_sync(0xffffffffu, bd, off);
            int   oi = __shfl_xor_sync(0xffffffffu, bi, off);
            if (od < bd || (od == bd && oi < bi)) { bd = od; bi = oi; }
        }
        float* op = out + (size_t)b * D * HW + hw;
        #pragma unroll
        for (int k = lane; k < 64; k += 32)
            op[(size_t)k * HW] = __ldg(cb + bi * D + k);
    }
}

extern "C" void kernel_launch(void* const* d_in, const int* in_sizes, int n_in,
                              void* d_out, int out_size) {
    const float* input    = (const float*)d_in[0];   // [16, 64, 64, 64] fp32 NCHW
    const float* codebook = (const float*)d_in[1];   // [1024, 64] fp32
    float*       out      = (float*)d_out;

    cudaFuncSetAttribute(vq_main, cudaFuncAttributeMaxDynamicSharedMemorySize, SMEM_REQ);
    vq_prep<<<256, 256>>>(codebook);
    vq_main<<<128, THREADS, SMEM_REQ>>>(input, codebook, out);
    vq_rf<<<128, 256>>>(input, codebook, out);
    vq_fb<<<128, 256>>>(input, codebook, out);
}